// round 3
// baseline (speedup 1.0000x reference)
#include <cuda_runtime.h>
#include <math.h>

#define DZ 32
#define DA 16
#define KMIX 8
#define DH 64
#define DG 64
#define TT 128
#define NB 256
#define LD 36    // padded stride, 16B-aligned rows
#define LDK 20   // padded stride for K (32x16), 16B-aligned rows

// output offsets (elements), per flattened reference tuple
#define OFF_ZF  0ull
#define OFF_PF  1048576ull
#define OFF_ZP  34603008ull
#define OFF_AF  35651584ull
#define OFF_AP  36175872ull
#define OFF_PP  36700160ull
#define OFF_ALP 70254592ull
#define OFF_AL  70516736ull
#define OFF_CL  104071168ull
#define OFF_ZM  120848384ull
#define OFF_LT  121896960ull
#define OFF_S   155451392ull

// C for slot 128 (not part of CL output)
__device__ __align__(16) float g_C128[NB * 512];

__device__ __forceinline__ float sigmoidf_(float x){ return 1.0f/(1.0f+expf(-x)); }

__device__ __forceinline__ float dot32(const float* __restrict__ a, const float* __restrict__ b){
    float4 s = make_float4(0.f,0.f,0.f,0.f);
    #pragma unroll
    for (int c = 0; c < 8; c++){
        float4 x = ((const float4*)a)[c];
        float4 y = ((const float4*)b)[c];
        s.x += x.x*y.x; s.y += x.y*y.y; s.z += x.z*y.z; s.w += x.w*y.w;
    }
    return (s.x+s.y)+(s.z+s.w);
}

// ================= alpha chain kernel: GRU + softmax + mixtures =================
// Writes AL, ALP, CL outputs directly; slot-128 C to g_C128.
__global__ void alpha_kernel(const float* __restrict__ a_seq, const float* __restrict__ h_obs,
                             const float* __restrict__ a0,
                             const float* __restrict__ Amat, const float* __restrict__ Cmat,
                             const float* __restrict__ Wx,   const float* __restrict__ Wh,
                             const float* __restrict__ bb,   const float* __restrict__ Wo,
                             const float* __restrict__ bo,   float* __restrict__ out)
{
    __shared__ float xv[80], h[64], hnew[64], gx[192], gh[192], alpha[8], part[192];
    const int b = blockIdx.x, tid = threadIdx.x;

    // h_ctx = mean_t h_obs
    {
        int d = tid & 63, c = tid >> 6;
        int t0 = c*43, t1 = (c==2) ? 128 : (t0+43);
        float s = 0.f;
        const float* hp = h_obs + ((size_t)b*TT + t0)*DH + d;
        #pragma unroll 4
        for (int t = t0; t < t1; t++, hp += DH) s += *hp;
        part[tid] = s;
    }
    if (tid < 16) xv[tid] = a0[tid];
    if (tid < 64) h[tid] = 0.f;
    __syncthreads();
    if (tid < 64) xv[16+tid] = (part[tid]+part[64+tid]+part[128+tid])*(1.0f/128.0f);
    __syncthreads();

    for (int s = 0; s <= TT; s++){
        // gx = [a, hctx] @ Wx + b ; gh = h @ Wh
        {
            float g = bb[tid];
            #pragma unroll 8
            for (int i = 0; i < 80; i++) g += xv[i]*Wx[i*192 + tid];
            gx[tid] = g;
            float g2 = 0.f;
            if (s > 0){
                #pragma unroll 8
                for (int d = 0; d < 64; d++) g2 += h[d]*Wh[d*192 + tid];
            }
            gh[tid] = g2;
        }
        __syncthreads();
        if (tid < 64){
            float r = sigmoidf_(gx[tid]      + gh[tid]);
            float u = sigmoidf_(gx[64 + tid] + gh[64 + tid]);
            float n = tanhf   (gx[128 + tid] + r*gh[128 + tid]);
            hnew[tid] = (1.f - u)*n + u*h[tid];
        }
        __syncthreads();
        if (tid < 8){
            float lg = bo[tid];
            #pragma unroll 8
            for (int d = 0; d < 64; d++) lg += hnew[d]*Wo[d*KMIX + tid];
            float m = lg;
            #pragma unroll
            for (int o = 4; o; o >>= 1) m = fmaxf(m, __shfl_xor_sync(0xFF, m, o));
            float ev = expf(lg - m), sm = ev;
            #pragma unroll
            for (int o = 4; o; o >>= 1) sm += __shfl_xor_sync(0xFF, sm, o);
            float al = ev/sm;
            alpha[tid] = al;
            if (s >= 1) out[OFF_ALP + ((size_t)b*TT + (s-1))*8 + tid] = al;
        }
        if (tid >= 64 && tid < 128) h[tid-64] = hnew[tid-64];
        __syncthreads();
        // mixtures
        if (s >= 1){
            #pragma unroll
            for (int r = 0; r < 6; r++){
                int e = tid + 192*r;
                if (e < 1024){
                    float v = 0.f;
                    #pragma unroll
                    for (int k = 0; k < KMIX; k++) v += alpha[k]*Amat[k*1024 + e];
                    out[OFF_AL + ((size_t)b*TT + (s-1))*1024 + e] = v;
                }
            }
        }
        {
            #pragma unroll
            for (int r = 0; r < 3; r++){
                int e = tid + 192*r;
                if (e < 512){
                    float v = 0.f;
                    #pragma unroll
                    for (int k = 0; k < KMIX; k++) v += alpha[k]*Cmat[k*512 + e];
                    if (s <= 127) out[OFF_CL + ((size_t)b*TT + s)*512 + e] = v;
                    else          g_C128[b*512 + e] = v;
                }
            }
        }
        if (tid < 16 && s < TT) xv[tid] = a_seq[((size_t)b*TT + s)*16 + tid];
        __syncthreads();
    }
}

// ================= main Kalman kernel =================
__global__ __launch_bounds__(256, 2)
void kf_kernel(const float* __restrict__ a_seq, float* __restrict__ out)
{
    __shared__ __align__(16) float P[DZ*LD], Pf[DZ*LD], Xb[DZ*LD], M2[DZ*LD], As[DZ*LD], CH[DZ*LD];
    __shared__ __align__(16) float Cb[2][DA*LD], CP[DA*LD], SG[DA*LD];
    __shared__ __align__(16) float Kg[DZ*LDK];
    __shared__ float zn[DZ], zfn[DZ], rvec[DA];

    const int tid  = threadIdx.x;
    const int wid  = tid >> 5;
    const int lane = tid & 31;
    const int b    = blockIdx.x;

    // prologue
    if (tid < DZ) zn[tid] = 0.f;
    #pragma unroll
    for (int k = 0; k < 4; k++){
        int e = tid + 256*k;
        int i = e >> 5, j = e & 31;
        P[i*LD + j] = (i == j) ? 10.f : 0.f;
    }
    #pragma unroll
    for (int k = 0; k < 2; k++){
        int e = tid + 256*k;
        int i = e >> 5, j = e & 31;
        Cb[0][i*LD + j] = out[OFF_CL + (size_t)b*TT*512 + e];
    }
    __syncthreads();

    for (int t = 0; t < TT; t++){
        const size_t bt = (size_t)b*TT + t;
        float* Ct = Cb[t & 1];
        float* Cn = Cb[(t+1) & 1];

        if (wid < 7){
            // ---- phA: CP = C_t * P  (128 thr)  ||  prefetch A_{t+1}, C_{t+1} (96 thr)
            if (tid < 128){
                int i = tid >> 3, jt = tid & 7;
                float4 acc = make_float4(0.f,0.f,0.f,0.f);
                const float* pr = P + jt*4;
                #pragma unroll
                for (int m = 0; m < 32; m++){
                    float c = Ct[i*LD + m];
                    float4 p4 = *(const float4*)(pr + m*LD);
                    acc.x += c*p4.x; acc.y += c*p4.y; acc.z += c*p4.z; acc.w += c*p4.w;
                }
                *(float4*)&CP[i*LD + jt*4] = acc;
            } else {
                int idx = tid - 128;
                #pragma unroll
                for (int r = 0; r < 4; r++){
                    int e = r*384 + idx*4;
                    float4 g;
                    if (e < 1024){
                        g = *(const float4*)(out + OFF_AL + bt*1024 + e);
                        int i = e >> 5, j = e & 31;
                        *(float4*)&As[i*LD + j] = g;
                    } else {
                        int e2 = e - 1024;
                        if (t < 127) g = *(const float4*)(out + OFF_CL + (bt+1)*512 + e2);
                        else         g = *(const float4*)(g_C128 + b*512 + e2);
                        int i = e2 >> 5, j = e2 & 31;
                        *(float4*)&Cn[i*LD + j] = g;
                    }
                }
            }
            asm volatile("bar.sync 1, 224;" ::: "memory");

            // ---- phB: S = CP C_t^T + 0.3I (store out)  ||  rvec
            float av = 0.f;
            if (tid >= 192 && tid < 208) av = a_seq[bt*DA + (tid-192)];
            {
                int e = tid;
                int i = e >> 4, j = e & 15;
                float s = ((i == j) ? 0.3f : 0.f) + dot32(CP + i*LD, Ct + j*LD);
                SG[i*LD + j] = s;
                out[OFF_S + bt*256 + e] = s;
            }
            if (tid < 32){
                int e = 224 + tid;
                int i = e >> 4, j = e & 15;
                float s = ((i == j) ? 0.3f : 0.f) + dot32(CP + i*LD, Ct + j*LD);
                SG[i*LD + j] = s;
                out[OFF_S + bt*256 + e] = s;
            }
            if (tid >= 192 && tid < 208){
                int la = tid - 192;
                rvec[la] = av - dot32(Ct + la*LD, zn);
            }
            __syncthreads();   // endB: warp7 takes S

            // ---- phC: deferred stores of step t-1 (warp7 does GJ)
            if (t > 0){
                const size_t btp = bt - 1;
                #pragma unroll
                for (int k = 0; k < 5; k++){
                    int e = tid + 224*k;
                    if (e < 1024){
                        int i = e >> 5, j = e & 31;
                        out[OFF_PF + btp*1024 + e] = Pf[i*LD + j];
                        out[OFF_PP + btp*1024 + e] = P[i*LD + j];
                        float l;
                        if (j < i)       l = CH[i*LD + j]*rsqrtf(CH[j*LD + j]);
                        else if (j == i) l = sqrtf(CH[i*LD + i]);
                        else             l = 0.f;
                        out[OFF_LT + btp*1024 + e] = l;
                    }
                }
            }
            __syncthreads();   // endC: Sinv ready

            // ---- phD: K = (CP)^T * Sinv  (128 thr)
            if (tid < 128){
                int i = tid >> 2, jt = tid & 3;
                float4 acc = make_float4(0.f,0.f,0.f,0.f);
                #pragma unroll
                for (int m = 0; m < 16; m++){
                    float c = CP[m*LD + i];
                    float4 s4 = *(const float4*)&SG[m*LD + 16 + jt*4];
                    acc.x += c*s4.x; acc.y += c*s4.y; acc.z += c*s4.z; acc.w += c*s4.w;
                }
                *(float4*)&Kg[i*LDK + jt*4] = acc;
            }
            asm volatile("bar.sync 1, 224;" ::: "memory");

            // ---- phE: X = K * CP  ;  zfn = zn + K rvec
            {
                #pragma unroll
                for (int q = 0; q < 2; q++){
                    int T = (q == 0) ? tid : (224 + tid);
                    if (q == 1 && tid >= 32) break;
                    int i = T >> 3, jt = T & 7;
                    float4 acc = make_float4(0.f,0.f,0.f,0.f);
                    #pragma unroll
                    for (int m = 0; m < 16; m++){
                        float kv = Kg[i*LDK + m];
                        float4 c4 = *(const float4*)&CP[m*LD + jt*4];
                        acc.x += kv*c4.x; acc.y += kv*c4.y; acc.z += kv*c4.z; acc.w += kv*c4.w;
                    }
                    *(float4*)&Xb[i*LD + jt*4] = acc;
                }
            }
            if (tid >= 192){
                int la = tid - 192;
                float s = zn[la];
                #pragma unroll
                for (int m = 0; m < 16; m++) s += Kg[la*LDK + m]*rvec[m];
                zfn[la] = s;
            }
            asm volatile("bar.sync 1, 224;" ::: "memory");

            // ---- phF: Pf = P - 0.5(X + X^T); CH = Pf + jitter; zp/afl/vec stores
            {
                #pragma unroll
                for (int q = 0; q < 2; q++){
                    int T = (q == 0) ? tid : (224 + tid);
                    if (q == 1 && tid >= 32) break;
                    int i = T >> 3, jt = T & 7;
                    float4 p4 = *(const float4*)&P[i*LD + jt*4];
                    float4 x4 = *(const float4*)&Xb[i*LD + jt*4];
                    float4 xt;
                    xt.x = Xb[(jt*4+0)*LD + i];
                    xt.y = Xb[(jt*4+1)*LD + i];
                    xt.z = Xb[(jt*4+2)*LD + i];
                    xt.w = Xb[(jt*4+3)*LD + i];
                    float4 pf4;
                    pf4.x = p4.x - 0.5f*(x4.x + xt.x);
                    pf4.y = p4.y - 0.5f*(x4.y + xt.y);
                    pf4.z = p4.z - 0.5f*(x4.z + xt.z);
                    pf4.w = p4.w - 0.5f*(x4.w + xt.w);
                    *(float4*)&Pf[i*LD + jt*4] = pf4;
                    float4 ch4 = pf4;
                    if (jt*4+0 == i) ch4.x += 2e-4f;
                    if (jt*4+1 == i) ch4.y += 2e-4f;
                    if (jt*4+2 == i) ch4.z += 2e-4f;
                    if (jt*4+3 == i) ch4.w += 2e-4f;
                    *(float4*)&CH[i*LD + jt*4] = ch4;
                }
            }
            if (tid >= 160 && tid < 192){
                int la = tid - 160;
                float zpv = dot32(As + la*LD, zfn);
                zn[la] = zpv;   // carry: znew_{t+1} = z_pred_t
                out[OFF_ZP + bt*32 + la] = zpv;
            } else if (tid >= 128 && tid < 144){
                int la = tid - 128;
                out[OFF_AF + bt*16 + la] = dot32(Ct + la*LD, zfn);
            } else if (tid >= 96 && tid < 128){
                int la = tid - 96;
                float z = zfn[la];
                out[OFF_ZF + bt*32 + la] = z;
                out[OFF_ZM + bt*32 + la] = z;
            }
            __syncthreads();   // endF: CH ready for warp7 Cholesky

            // ---- phG: M2 = A_{t+1} * Pf
            {
                #pragma unroll
                for (int q = 0; q < 2; q++){
                    int T = (q == 0) ? tid : (224 + tid);
                    if (q == 1 && tid >= 32) break;
                    int i = T >> 3, jt = T & 7;
                    float4 acc = make_float4(0.f,0.f,0.f,0.f);
                    const float* pr = Pf + jt*4;
                    #pragma unroll
                    for (int m = 0; m < 32; m++){
                        float a = As[i*LD + m];
                        float4 p4 = *(const float4*)(pr + m*LD);
                        acc.x += a*p4.x; acc.y += a*p4.y; acc.z += a*p4.z; acc.w += a*p4.w;
                    }
                    *(float4*)&M2[i*LD + jt*4] = acc;
                }
            }
            asm volatile("bar.sync 1, 224;" ::: "memory");

            // ---- phH: RAW = M2 * A^T (into Xb) ; ap
            {
                #pragma unroll
                for (int k = 0; k < 5; k++){
                    int e = tid + 224*k;
                    if (e < 1024){
                        int i = e >> 5, j = e & 31;
                        Xb[i*LD + j] = dot32(M2 + i*LD, As + j*LD);
                    }
                }
            }
            if (tid >= 128 && tid < 144){
                int la = tid - 128;
                out[OFF_AP + bt*16 + la] = dot32(Cn + la*LD, zn);
            }
            asm volatile("bar.sync 1, 224;" ::: "memory");

            // ---- phI: P = sym(RAW) + Q (carry)
            {
                #pragma unroll
                for (int k = 0; k < 5; k++){
                    int e = tid + 224*k;
                    if (e < 1024){
                        int i = e >> 5, j = e & 31;
                        P[i*LD + j] = 0.5f*(Xb[i*LD + j] + Xb[j*LD + i]) + ((i == j) ? 0.2f : 0.f);
                    }
                }
            }
            asm volatile("bar.sync 1, 224;" ::: "memory");
        } else {
            // ================= warp 7: serial specialist =================
            __syncthreads();   // endB: S ready
            // GJ inversion of S (registers + shuffle)
            {
                float c[16];
                #pragma unroll
                for (int i = 0; i < 16; i++)
                    c[i] = (lane < 16) ? SG[i*LD + lane] : ((i == lane-16) ? 1.f : 0.f);
                #pragma unroll
                for (int p = 0; p < 16; p++){
                    float spp = __shfl_sync(0xffffffffu, c[p], p);
                    float inv = 1.0f/spp;
                    float pivj = c[p]*inv;
                    #pragma unroll
                    for (int i = 0; i < 16; i++){
                        float fac = __shfl_sync(0xffffffffu, c[i], p);
                        if (i != p) c[i] -= fac*pivj;
                    }
                    c[p] = pivj;
                }
                if (lane >= 16){
                    #pragma unroll
                    for (int i = 0; i < 16; i++) SG[i*LD + lane] = c[i];
                }
            }
            __syncthreads();   // endC: hand Sinv to warps 0-6
            __syncthreads();   // endF: CH ready
            // Cholesky trailing update on CH (overlaps phG..next phB)
            for (int j = 0; j < DZ-1; j++){
                float inv = __fdividef(1.0f, CH[j*LD + j]);
                int kk = j + 1 + lane;
                if (kk < DZ){
                    float ckj = CH[kk*LD + j]*inv;
                    for (int ii = kk; ii < DZ; ii++)
                        CH[ii*LD + kk] -= CH[ii*LD + j]*ckj;
                }
                __syncwarp();
            }
        }
    }

    // epilogue: stores for t = 127
    __syncthreads();
    {
        const size_t btl = (size_t)b*TT + 127;
        #pragma unroll
        for (int k = 0; k < 4; k++){
            int e = tid + 256*k;
            int i = e >> 5, j = e & 31;
            out[OFF_PF + btl*1024 + e] = Pf[i*LD + j];
            out[OFF_PP + btl*1024 + e] = P[i*LD + j];
            float l;
            if (j < i)       l = CH[i*LD + j]*rsqrtf(CH[j*LD + j]);
            else if (j == i) l = sqrtf(CH[i*LD + i]);
            else             l = 0.f;
            out[OFF_LT + btl*1024 + e] = l;
        }
    }
}

extern "C" void kernel_launch(void* const* d_in, const int* in_sizes, int n_in,
                              void* d_out, int out_size) {
    const float* a_seq = (const float*)d_in[0];
    const float* h_obs = (const float*)d_in[1];
    const float* Amat  = (const float*)d_in[2];
    const float* Cmat  = (const float*)d_in[3];
    const float* a0    = (const float*)d_in[4];
    const float* Wx    = (const float*)d_in[5];
    const float* Wh    = (const float*)d_in[6];
    const float* bb    = (const float*)d_in[7];
    const float* Wo    = (const float*)d_in[8];
    const float* bo    = (const float*)d_in[9];
    float* out = (float*)d_out;

    alpha_kernel<<<NB, 192>>>(a_seq, h_obs, a0, Amat, Cmat, Wx, Wh, bb, Wo, bo, out);
    kf_kernel<<<NB, 256>>>(a_seq, out);
}

// round 4
// speedup vs baseline: 1.0031x; 1.0031x over previous
#include <cuda_runtime.h>
#include <math.h>

#define DZ 32
#define DA 16
#define KMIX 8
#define DH 64
#define DG 64
#define TT 128
#define NB 256
#define LD 36    // padded stride, 16B-aligned rows
#define LDK 20   // padded stride for K (32x16), 16B-aligned rows

// output offsets (elements), per flattened reference tuple
#define OFF_ZF  0ull
#define OFF_PF  1048576ull
#define OFF_ZP  34603008ull
#define OFF_AF  35651584ull
#define OFF_AP  36175872ull
#define OFF_PP  36700160ull
#define OFF_ALP 70254592ull
#define OFF_AL  70516736ull
#define OFF_CL  104071168ull
#define OFF_ZM  120848384ull
#define OFF_LT  121896960ull
#define OFF_S   155451392ull

// C for slot 128 (not part of CL output)
__device__ __align__(16) float g_C128[NB * 512];

__device__ __forceinline__ float sigmoidf_(float x){ return 1.0f/(1.0f+expf(-x)); }

__device__ __forceinline__ float dot32(const float* __restrict__ a, const float* __restrict__ b){
    float4 s = make_float4(0.f,0.f,0.f,0.f);
    #pragma unroll
    for (int c = 0; c < 8; c++){
        float4 x = ((const float4*)a)[c];
        float4 y = ((const float4*)b)[c];
        s.x += x.x*y.x; s.y += x.y*y.y; s.z += x.z*y.z; s.w += x.w*y.w;
    }
    return (s.x+s.y)+(s.z+s.w);
}

// ================= alpha chain kernel: GRU + softmax + mixtures =================
// Writes AL, ALP, CL outputs directly; slot-128 C to g_C128.
__global__ void alpha_kernel(const float* __restrict__ a_seq, const float* __restrict__ h_obs,
                             const float* __restrict__ a0,
                             const float* __restrict__ Amat, const float* __restrict__ Cmat,
                             const float* __restrict__ Wx,   const float* __restrict__ Wh,
                             const float* __restrict__ bb,   const float* __restrict__ Wo,
                             const float* __restrict__ bo,   float* __restrict__ out)
{
    __shared__ float xv[80], h[64], hnew[64], gx[192], gh[192], alpha[8], part[192];
    const int b = blockIdx.x, tid = threadIdx.x;

    // h_ctx = mean_t h_obs
    {
        int d = tid & 63, c = tid >> 6;
        int t0 = c*43, t1 = (c==2) ? 128 : (t0+43);
        float s = 0.f;
        const float* hp = h_obs + ((size_t)b*TT + t0)*DH + d;
        #pragma unroll 4
        for (int t = t0; t < t1; t++, hp += DH) s += *hp;
        part[tid] = s;
    }
    if (tid < 16) xv[tid] = a0[tid];
    if (tid < 64) h[tid] = 0.f;
    __syncthreads();
    if (tid < 64) xv[16+tid] = (part[tid]+part[64+tid]+part[128+tid])*(1.0f/128.0f);
    __syncthreads();

    for (int s = 0; s <= TT; s++){
        // gx = [a, hctx] @ Wx + b ; gh = h @ Wh
        {
            float g = bb[tid];
            #pragma unroll 8
            for (int i = 0; i < 80; i++) g += xv[i]*Wx[i*192 + tid];
            gx[tid] = g;
            float g2 = 0.f;
            if (s > 0){
                #pragma unroll 8
                for (int d = 0; d < 64; d++) g2 += h[d]*Wh[d*192 + tid];
            }
            gh[tid] = g2;
        }
        __syncthreads();
        if (tid < 64){
            float r = sigmoidf_(gx[tid]      + gh[tid]);
            float u = sigmoidf_(gx[64 + tid] + gh[64 + tid]);
            float n = tanhf   (gx[128 + tid] + r*gh[128 + tid]);
            hnew[tid] = (1.f - u)*n + u*h[tid];
        }
        __syncthreads();
        if (tid < 8){
            float lg = bo[tid];
            #pragma unroll 8
            for (int d = 0; d < 64; d++) lg += hnew[d]*Wo[d*KMIX + tid];
            float m = lg;
            #pragma unroll
            for (int o = 4; o; o >>= 1) m = fmaxf(m, __shfl_xor_sync(0xFF, m, o));
            float ev = expf(lg - m), sm = ev;
            #pragma unroll
            for (int o = 4; o; o >>= 1) sm += __shfl_xor_sync(0xFF, sm, o);
            float al = ev/sm;
            alpha[tid] = al;
            if (s >= 1) out[OFF_ALP + ((size_t)b*TT + (s-1))*8 + tid] = al;
        }
        if (tid >= 64 && tid < 128) h[tid-64] = hnew[tid-64];
        __syncthreads();
        // mixtures
        if (s >= 1){
            #pragma unroll
            for (int r = 0; r < 6; r++){
                int e = tid + 192*r;
                if (e < 1024){
                    float v = 0.f;
                    #pragma unroll
                    for (int k = 0; k < KMIX; k++) v += alpha[k]*Amat[k*1024 + e];
                    out[OFF_AL + ((size_t)b*TT + (s-1))*1024 + e] = v;
                }
            }
        }
        {
            #pragma unroll
            for (int r = 0; r < 3; r++){
                int e = tid + 192*r;
                if (e < 512){
                    float v = 0.f;
                    #pragma unroll
                    for (int k = 0; k < KMIX; k++) v += alpha[k]*Cmat[k*512 + e];
                    if (s <= 127) out[OFF_CL + ((size_t)b*TT + s)*512 + e] = v;
                    else          g_C128[b*512 + e] = v;
                }
            }
        }
        if (tid < 16 && s < TT) xv[tid] = a_seq[((size_t)b*TT + s)*16 + tid];
        __syncthreads();
    }
}

// ================= main Kalman kernel =================
__global__ __launch_bounds__(256, 2)
void kf_kernel(const float* __restrict__ a_seq, float* __restrict__ out)
{
    __shared__ __align__(16) float P[DZ*LD], Pf[DZ*LD], Xb[DZ*LD], M2[DZ*LD], As[DZ*LD], CH[DZ*LD];
    __shared__ __align__(16) float Cb[2][DA*LD], CP[DA*LD], SG[DA*LD];
    __shared__ __align__(16) float Kg[DZ*LDK];
    __shared__ float zn[DZ], zfn[DZ], rvec[DA];

    const int tid  = threadIdx.x;
    const int wid  = tid >> 5;
    const int lane = tid & 31;
    const int b    = blockIdx.x;

    // prologue
    if (tid < DZ) zn[tid] = 0.f;
    #pragma unroll
    for (int k = 0; k < 4; k++){
        int e = tid + 256*k;
        int i = e >> 5, j = e & 31;
        P[i*LD + j] = (i == j) ? 10.f : 0.f;
    }
    #pragma unroll
    for (int k = 0; k < 2; k++){
        int e = tid + 256*k;
        int i = e >> 5, j = e & 31;
        Cb[0][i*LD + j] = out[OFF_CL + (size_t)b*TT*512 + e];
    }
    __syncthreads();

    for (int t = 0; t < TT; t++){
        const size_t bt = (size_t)b*TT + t;
        float* Ct = Cb[t & 1];
        float* Cn = Cb[(t+1) & 1];

        if (wid < 7){
            // ---- phA: CP = C_t * P  (128 thr)  ||  prefetch A_{t+1}, C_{t+1} (96 thr)
            if (tid < 128){
                int i = tid >> 3, jt = tid & 7;
                float4 acc = make_float4(0.f,0.f,0.f,0.f);
                const float* pr = P + jt*4;
                #pragma unroll
                for (int m = 0; m < 32; m++){
                    float c = Ct[i*LD + m];
                    float4 p4 = *(const float4*)(pr + m*LD);
                    acc.x += c*p4.x; acc.y += c*p4.y; acc.z += c*p4.z; acc.w += c*p4.w;
                }
                *(float4*)&CP[i*LD + jt*4] = acc;
            } else {
                int idx = tid - 128;
                #pragma unroll
                for (int r = 0; r < 4; r++){
                    int e = r*384 + idx*4;
                    float4 g;
                    if (e < 1024){
                        g = *(const float4*)(out + OFF_AL + bt*1024 + e);
                        int i = e >> 5, j = e & 31;
                        *(float4*)&As[i*LD + j] = g;
                    } else {
                        int e2 = e - 1024;
                        if (t < 127) g = *(const float4*)(out + OFF_CL + (bt+1)*512 + e2);
                        else         g = *(const float4*)(g_C128 + b*512 + e2);
                        int i = e2 >> 5, j = e2 & 31;
                        *(float4*)&Cn[i*LD + j] = g;
                    }
                }
            }
            asm volatile("bar.sync 1, 224;" ::: "memory");

            // ---- phB: S = CP C_t^T + 0.3I (store out)  ||  rvec
            float av = 0.f;
            if (tid >= 192 && tid < 208) av = a_seq[bt*DA + (tid-192)];
            {
                int e = tid;
                int i = e >> 4, j = e & 15;
                float s = ((i == j) ? 0.3f : 0.f) + dot32(CP + i*LD, Ct + j*LD);
                SG[i*LD + j] = s;
                out[OFF_S + bt*256 + e] = s;
            }
            if (tid < 32){
                int e = 224 + tid;
                int i = e >> 4, j = e & 15;
                float s = ((i == j) ? 0.3f : 0.f) + dot32(CP + i*LD, Ct + j*LD);
                SG[i*LD + j] = s;
                out[OFF_S + bt*256 + e] = s;
            }
            if (tid >= 192 && tid < 208){
                int la = tid - 192;
                rvec[la] = av - dot32(Ct + la*LD, zn);
            }
            __syncthreads();   // endB: warp7 takes S

            // ---- phC: deferred stores of step t-1 (warp7 does GJ)
            if (t > 0){
                const size_t btp = bt - 1;
                #pragma unroll
                for (int k = 0; k < 5; k++){
                    int e = tid + 224*k;
                    if (e < 1024){
                        int i = e >> 5, j = e & 31;
                        out[OFF_PF + btp*1024 + e] = Pf[i*LD + j];
                        out[OFF_PP + btp*1024 + e] = P[i*LD + j];
                        float l;
                        if (j < i)       l = CH[i*LD + j]*rsqrtf(CH[j*LD + j]);
                        else if (j == i) l = sqrtf(CH[i*LD + i]);
                        else             l = 0.f;
                        out[OFF_LT + btp*1024 + e] = l;
                    }
                }
            }
            __syncthreads();   // endC: Sinv ready

            // ---- phD: K = (CP)^T * Sinv  (128 thr)
            if (tid < 128){
                int i = tid >> 2, jt = tid & 3;
                float4 acc = make_float4(0.f,0.f,0.f,0.f);
                #pragma unroll
                for (int m = 0; m < 16; m++){
                    float c = CP[m*LD + i];
                    float4 s4 = *(const float4*)&SG[m*LD + 16 + jt*4];
                    acc.x += c*s4.x; acc.y += c*s4.y; acc.z += c*s4.z; acc.w += c*s4.w;
                }
                *(float4*)&Kg[i*LDK + jt*4] = acc;
            }
            asm volatile("bar.sync 1, 224;" ::: "memory");

            // ---- phE: X = K * CP  ;  zfn = zn + K rvec
            {
                #pragma unroll
                for (int q = 0; q < 2; q++){
                    int T = (q == 0) ? tid : (224 + tid);
                    if (q == 1 && tid >= 32) break;
                    int i = T >> 3, jt = T & 7;
                    float4 acc = make_float4(0.f,0.f,0.f,0.f);
                    #pragma unroll
                    for (int m = 0; m < 16; m++){
                        float kv = Kg[i*LDK + m];
                        float4 c4 = *(const float4*)&CP[m*LD + jt*4];
                        acc.x += kv*c4.x; acc.y += kv*c4.y; acc.z += kv*c4.z; acc.w += kv*c4.w;
                    }
                    *(float4*)&Xb[i*LD + jt*4] = acc;
                }
            }
            if (tid >= 192){
                int la = tid - 192;
                float s = zn[la];
                #pragma unroll
                for (int m = 0; m < 16; m++) s += Kg[la*LDK + m]*rvec[m];
                zfn[la] = s;
            }
            asm volatile("bar.sync 1, 224;" ::: "memory");

            // ---- phF: Pf = P - 0.5(X + X^T); CH = Pf + jitter; zp/afl/vec stores
            {
                #pragma unroll
                for (int q = 0; q < 2; q++){
                    int T = (q == 0) ? tid : (224 + tid);
                    if (q == 1 && tid >= 32) break;
                    int i = T >> 3, jt = T & 7;
                    float4 p4 = *(const float4*)&P[i*LD + jt*4];
                    float4 x4 = *(const float4*)&Xb[i*LD + jt*4];
                    float4 xt;
                    xt.x = Xb[(jt*4+0)*LD + i];
                    xt.y = Xb[(jt*4+1)*LD + i];
                    xt.z = Xb[(jt*4+2)*LD + i];
                    xt.w = Xb[(jt*4+3)*LD + i];
                    float4 pf4;
                    pf4.x = p4.x - 0.5f*(x4.x + xt.x);
                    pf4.y = p4.y - 0.5f*(x4.y + xt.y);
                    pf4.z = p4.z - 0.5f*(x4.z + xt.z);
                    pf4.w = p4.w - 0.5f*(x4.w + xt.w);
                    *(float4*)&Pf[i*LD + jt*4] = pf4;
                    float4 ch4 = pf4;
                    if (jt*4+0 == i) ch4.x += 2e-4f;
                    if (jt*4+1 == i) ch4.y += 2e-4f;
                    if (jt*4+2 == i) ch4.z += 2e-4f;
                    if (jt*4+3 == i) ch4.w += 2e-4f;
                    *(float4*)&CH[i*LD + jt*4] = ch4;
                }
            }
            if (tid >= 160 && tid < 192){
                int la = tid - 160;
                float zpv = dot32(As + la*LD, zfn);
                zn[la] = zpv;   // carry: znew_{t+1} = z_pred_t
                out[OFF_ZP + bt*32 + la] = zpv;
            } else if (tid >= 128 && tid < 144){
                int la = tid - 128;
                out[OFF_AF + bt*16 + la] = dot32(Ct + la*LD, zfn);
            } else if (tid >= 96 && tid < 128){
                int la = tid - 96;
                float z = zfn[la];
                out[OFF_ZF + bt*32 + la] = z;
                out[OFF_ZM + bt*32 + la] = z;
            }
            __syncthreads();   // endF: CH ready for warp7 Cholesky

            // ---- phG: M2 = A_{t+1} * Pf
            {
                #pragma unroll
                for (int q = 0; q < 2; q++){
                    int T = (q == 0) ? tid : (224 + tid);
                    if (q == 1 && tid >= 32) break;
                    int i = T >> 3, jt = T & 7;
                    float4 acc = make_float4(0.f,0.f,0.f,0.f);
                    const float* pr = Pf + jt*4;
                    #pragma unroll
                    for (int m = 0; m < 32; m++){
                        float a = As[i*LD + m];
                        float4 p4 = *(const float4*)(pr + m*LD);
                        acc.x += a*p4.x; acc.y += a*p4.y; acc.z += a*p4.z; acc.w += a*p4.w;
                    }
                    *(float4*)&M2[i*LD + jt*4] = acc;
                }
            }
            asm volatile("bar.sync 1, 224;" ::: "memory");

            // ---- phH: RAW = M2 * A^T (into Xb) ; ap
            {
                #pragma unroll
                for (int k = 0; k < 5; k++){
                    int e = tid + 224*k;
                    if (e < 1024){
                        int i = e >> 5, j = e & 31;
                        Xb[i*LD + j] = dot32(M2 + i*LD, As + j*LD);
                    }
                }
            }
            if (tid >= 128 && tid < 144){
                int la = tid - 128;
                out[OFF_AP + bt*16 + la] = dot32(Cn + la*LD, zn);
            }
            asm volatile("bar.sync 1, 224;" ::: "memory");

            // ---- phI: P = sym(RAW) + Q (carry)
            {
                #pragma unroll
                for (int k = 0; k < 5; k++){
                    int e = tid + 224*k;
                    if (e < 1024){
                        int i = e >> 5, j = e & 31;
                        P[i*LD + j] = 0.5f*(Xb[i*LD + j] + Xb[j*LD + i]) + ((i == j) ? 0.2f : 0.f);
                    }
                }
            }
            asm volatile("bar.sync 1, 224;" ::: "memory");
        } else {
            // ================= warp 7: serial specialist =================
            __syncthreads();   // endB: S ready
            // GJ inversion of S (registers + shuffle)
            {
                float c[16];
                #pragma unroll
                for (int i = 0; i < 16; i++)
                    c[i] = (lane < 16) ? SG[i*LD + lane] : ((i == lane-16) ? 1.f : 0.f);
                #pragma unroll
                for (int p = 0; p < 16; p++){
                    float spp = __shfl_sync(0xffffffffu, c[p], p);
                    float inv = 1.0f/spp;
                    float pivj = c[p]*inv;
                    #pragma unroll
                    for (int i = 0; i < 16; i++){
                        float fac = __shfl_sync(0xffffffffu, c[i], p);
                        if (i != p) c[i] -= fac*pivj;
                    }
                    c[p] = pivj;
                }
                if (lane >= 16){
                    #pragma unroll
                    for (int i = 0; i < 16; i++) SG[i*LD + lane] = c[i];
                }
            }
            __syncthreads();   // endC: hand Sinv to warps 0-6
            __syncthreads();   // endF: CH ready
            // Cholesky trailing update on CH (overlaps phG..next phB)
            for (int j = 0; j < DZ-1; j++){
                float inv = __fdividef(1.0f, CH[j*LD + j]);
                int kk = j + 1 + lane;
                if (kk < DZ){
                    float ckj = CH[kk*LD + j]*inv;
                    for (int ii = kk; ii < DZ; ii++)
                        CH[ii*LD + kk] -= CH[ii*LD + j]*ckj;
                }
                __syncwarp();
            }
        }
    }

    // epilogue: stores for t = 127
    __syncthreads();
    {
        const size_t btl = (size_t)b*TT + 127;
        #pragma unroll
        for (int k = 0; k < 4; k++){
            int e = tid + 256*k;
            int i = e >> 5, j = e & 31;
            out[OFF_PF + btl*1024 + e] = Pf[i*LD + j];
            out[OFF_PP + btl*1024 + e] = P[i*LD + j];
            float l;
            if (j < i)       l = CH[i*LD + j]*rsqrtf(CH[j*LD + j]);
            else if (j == i) l = sqrtf(CH[i*LD + i]);
            else             l = 0.f;
            out[OFF_LT + btl*1024 + e] = l;
        }
    }
}

extern "C" void kernel_launch(void* const* d_in, const int* in_sizes, int n_in,
                              void* d_out, int out_size) {
    const float* a_seq = (const float*)d_in[0];
    const float* h_obs = (const float*)d_in[1];
    const float* Amat  = (const float*)d_in[2];
    const float* Cmat  = (const float*)d_in[3];
    const float* a0    = (const float*)d_in[4];
    const float* Wx    = (const float*)d_in[5];
    const float* Wh    = (const float*)d_in[6];
    const float* bb    = (const float*)d_in[7];
    const float* Wo    = (const float*)d_in[8];
    const float* bo    = (const float*)d_in[9];
    float* out = (float*)d_out;

    alpha_kernel<<<NB, 192>>>(a_seq, h_obs, a0, Amat, Cmat, Wx, Wh, bb, Wo, bo, out);
    kf_kernel<<<NB, 256>>>(a_seq, out);
}